// round 10
// baseline (speedup 1.0000x reference)
#include <cuda_runtime.h>
#include <cuda_fp16.h>
#include <cstdint>

// Problem constants (fixed by the dataset)
#define BB 32      // batch
#define II 2048    // input capsules
#define CC 16      // input atoms (contraction dim)
#define DD 32      // output capsules
#define AA 16      // output atoms
#define OO 512     // DD*AA
#define BO (BB*OO) // 16384
#define NBMAX 160
#define NT 1024

typedef unsigned long long ull;

// Scratch (static __device__ arrays: no dynamic allocation)
__device__ __half g_votes[(size_t)II * BB * OO];     // [i][b][o] fp16, 67 MB
__device__ float  g_part[(size_t)NBMAX * BO];        // per-block partials, 10.5 MB
__device__ float  g_actS[BO];                        // act0, then act0+act1
__device__ unsigned g_count;                          // barrier arrive counter (self-resetting)
__device__ volatile unsigned g_sense;                 // barrier generation (monotonic)

// ---------------- packed f32x2 helpers ----------------
__device__ __forceinline__ ull pack2(float lo, float hi) {
    ull r; asm("mov.b64 %0, {%1,%2};" : "=l"(r) : "f"(lo), "f"(hi)); return r;
}
__device__ __forceinline__ void unpack2(ull v, float& lo, float& hi) {
    asm("mov.b64 {%0,%1}, %2;" : "=f"(lo), "=f"(hi) : "l"(v));
}
__device__ __forceinline__ void fma2(ull& d, ull a, ull b) {
    asm("fma.rn.f32x2 %0, %1, %2, %0;" : "+l"(d) : "l"(a), "l"(b));
}
__device__ __forceinline__ void add2(ull& d, ull a) {
    asm("add.rn.f32x2 %0, %1, %0;" : "+l"(d) : "l"(a));
}

// ---------------- TMA bulk copy + mbarrier helpers ----------------
__device__ __forceinline__ void bulk_g2s(unsigned sdst, const void* gsrc,
                                         unsigned bytes, unsigned mbar) {
    asm volatile(
        "cp.async.bulk.shared::cluster.global.mbarrier::complete_tx::bytes [%0], [%1], %2, [%3];"
        :: "r"(sdst), "l"(gsrc), "r"(bytes), "r"(mbar) : "memory");
}
#define MBAR_INIT(a, c) \
    asm volatile("mbarrier.init.shared.b64 [%0], %1;" :: "r"(a), "r"(c) : "memory")
#define MBAR_EXPECT(a, b) \
    asm volatile("mbarrier.arrive.expect_tx.shared.b64 _, [%0], %1;" :: "r"(a), "r"(b) : "memory")
__device__ __forceinline__ void mbar_wait(unsigned addr, unsigned parity) {
    asm volatile(
        "{\n\t"
        ".reg .pred P;\n"
        "WAITLP_%=:\n\t"
        "mbarrier.try_wait.parity.acquire.cta.shared::cta.b64 P, [%0], %1, 0x989680;\n\t"
        "@P bra.uni WDONE_%=;\n\t"
        "bra.uni WAITLP_%=;\n"
        "WDONE_%=:\n\t"
        "}"
        :: "r"(addr), "r"(parity) : "memory");
}

// smem layout: W buffers [2][32KB] @0, x buffers [2][2KB] @65536, mbars @69632
#define WBUF_F4   2048
#define XBUF_OFF  65536
#define MBAR_OFF  69632
#define SMEM_TOTAL 69664
#define TX_BYTES  (32768 + BB * 64)   // W tile + 32 x rows = 34816

// ---------------------------------------------------------------------------
// Software grid barrier (sense-reversing). nb blocks co-resident (1/SM).
// ---------------------------------------------------------------------------
__device__ __forceinline__ void grid_sync(int nb) {
    __syncthreads();
    if (threadIdx.x == 0) {
        unsigned gen = g_sense;
        __threadfence();
        if (atomicAdd(&g_count, 1u) == (unsigned)(nb - 1)) {
            g_count = 0;
            __threadfence();
            g_sense = gen + 1;
        } else {
            while (g_sense == gen) __nanosleep(32);
        }
        __threadfence();
    }
    __syncthreads();
}

// ---------------------------------------------------------------------------
// Squash phase: blocks 0..127 active; block -> (b = bx>>2, oq4 = bx&3).
// 1024 threads = 32 float4-cols x 32 k-slices; smem tree; lane groups of 4
// = one 16-atom capsule. Fixed order -> deterministic.
// ---------------------------------------------------------------------------
__device__ __forceinline__ void squash_phase(char* smem, int nb, float scale,
                                             const float* __restrict__ bias,
                                             float* __restrict__ dst, int accumulate) {
    if (blockIdx.x < 128) {
        float4* red = (float4*)smem;                 // [32][33] float4 (17 KB)
        const int b    = blockIdx.x >> 2;
        const int oq4  = blockIdx.x & 3;
        const int col  = threadIdx.x & 31;
        const int ks   = threadIdx.x >> 5;
        const int gcol = b * 128 + oq4 * 32 + col;   // global float4 column
        const float4* gp = (const float4*)g_part;

        float4 s = make_float4(0.f, 0.f, 0.f, 0.f);
        for (int k = ks; k < nb; k += 32) {
            float4 v = gp[(size_t)k * (BO / 4) + gcol];
            s.x += v.x; s.y += v.y; s.z += v.z; s.w += v.w;
        }
        red[ks * 33 + col] = s;
        __syncthreads();

        if (threadIdx.x < 32) {
            float4 sum = red[col];
#pragma unroll
            for (int j = 1; j < 32; j++) {
                float4 v = red[j * 33 + col];
                sum.x += v.x; sum.y += v.y; sum.z += v.z; sum.w += v.w;
            }
            const float4 bi = ((const float4*)bias)[oq4 * 32 + col];
            float4 val;
            val.x = fmaf(sum.x, scale, bi.x);
            val.y = fmaf(sum.y, scale, bi.y);
            val.z = fmaf(sum.z, scale, bi.z);
            val.w = fmaf(sum.w, scale, bi.w);

            float n2 = (val.x * val.x + val.y * val.y) + (val.z * val.z + val.w * val.w);
            n2 += __shfl_xor_sync(0xffffffffu, n2, 1);
            n2 += __shfl_xor_sync(0xffffffffu, n2, 2);
            const float f = sqrtf(n2) / (1.f + n2);

            float4* dp = (float4*)dst + gcol;
            if (accumulate) {
                float4 cur = *dp;
                cur.x = fmaf(val.x, f, cur.x); cur.y = fmaf(val.y, f, cur.y);
                cur.z = fmaf(val.z, f, cur.z); cur.w = fmaf(val.w, f, cur.w);
                *dp = cur;
            } else {
                *dp = make_float4(val.x * f, val.y * f, val.z * f, val.w * f);
            }
        }
    }
    __syncthreads();
}

// ---------------------------------------------------------------------------
// Route phase: block bx owns i in [ilo, ihi); warp = one b; lane = one d.
// STREAM=1 (pass 2): __ldcs streaming (votes dead after; keeps DRAM quiet).
// Prefetch next i before the softmax chain; dot and accumulate in f32x2.
// ---------------------------------------------------------------------------
template <int STREAM>
__device__ __forceinline__ void route_phase(int nb) {
    const int b    = threadIdx.x >> 5;
    const int lane = threadIdx.x & 31;
    const int bx   = blockIdx.x;
    const int ilo  = (bx * II) / nb;
    const int ihi  = ((bx + 1) * II) / nb;
    const int d    = lane;

    ull arp[8];
    {
        const float4* ap = (const float4*)(g_actS + (b * DD + d) * AA);
        float4 a0 = ap[0], a1 = ap[1], a2 = ap[2], a3 = ap[3];
        arp[0] = pack2(a0.x, a0.y); arp[1] = pack2(a0.z, a0.w);
        arp[2] = pack2(a1.x, a1.y); arp[3] = pack2(a1.z, a1.w);
        arp[4] = pack2(a2.x, a2.y); arp[5] = pack2(a2.z, a2.w);
        arp[6] = pack2(a3.x, a3.y); arp[7] = pack2(a3.z, a3.w);
    }

    ull acc[8];
#pragma unroll
    for (int k = 0; k < 8; k++) acc[k] = 0ull;

    const uint4* vbase = (const uint4*)(g_votes + (size_t)b * OO + d * 16);
    const int stride = (BB * OO) / 8;                 // uint4 stride per i
    uint4 p0 = STREAM ? __ldcs(vbase + (size_t)ilo * stride)
                      : __ldg(vbase + (size_t)ilo * stride);
    uint4 p1 = STREAM ? __ldcs(vbase + (size_t)ilo * stride + 1)
                      : __ldg(vbase + (size_t)ilo * stride + 1);

    for (int i = ilo; i < ihi; i++) {
        uint4 c0 = p0, c1 = p1;
        if (i + 1 < ihi) {                    // prefetch next i before the chain
            const uint4* np = vbase + (size_t)(i + 1) * stride;
            p0 = STREAM ? __ldcs(np)     : __ldg(np);
            p1 = STREAM ? __ldcs(np + 1) : __ldg(np + 1);
        }

        ull vpk[8];
        {
            const __half2* h0 = (const __half2*)&c0;
            const __half2* h1 = (const __half2*)&c1;
#pragma unroll
            for (int j = 0; j < 4; j++) {
                float2 f = __half22float2(h0[j]); vpk[j]     = pack2(f.x, f.y);
                float2 g = __half22float2(h1[j]); vpk[4 + j] = pack2(g.x, g.y);
            }
        }

        ull u2 = 0ull;
#pragma unroll
        for (int k = 0; k < 8; k++) fma2(u2, vpk[k], arp[k]);
        float ulo, uhi; unpack2(u2, ulo, uhi);
        const float u = ulo + uhi;

        // softmax over d (32 lanes); |u| small enough to skip max-subtract
        float e = __expf(u);
        float s = e;
#pragma unroll
        for (int o = 16; o >= 1; o >>= 1) s += __shfl_xor_sync(0xffffffffu, s, o);
        const float r = __fdividef(e, s);
        const ull rr = pack2(r, r);
#pragma unroll
        for (int k = 0; k < 8; k++) fma2(acc[k], rr, vpk[k]);
    }

    float* dst = g_part + (size_t)bx * BO + (b * DD + d) * AA;
#pragma unroll
    for (int k = 0; k < 4; k++) {
        float l0, h0, l1, h1;
        unpack2(acc[2 * k], l0, h0);
        unpack2(acc[2 * k + 1], l1, h1);
        ((float4*)dst)[k] = make_float4(l0, h0, l1, h1);
    }
}

// ---------------------------------------------------------------------------
// Fused persistent kernel: votes -> squash0 -> route1 -> squash1 -> route2
// -> squash2, with software grid barriers between phases.
// ---------------------------------------------------------------------------
__global__ __launch_bounds__(NT, 1) void caps_kernel(const float* __restrict__ x,
                                                     const float* __restrict__ w,
                                                     const float* __restrict__ bias,
                                                     float* __restrict__ out,
                                                     int nb) {
    extern __shared__ __align__(16) char smem[];

    // ================= Phase 1: votes =================
    // 32 warps = 4 o-quarters x 8 b-groups(4 b); lane owns 4 consecutive o.
    // W + x tiles arrive via cp.async.bulk (TMA): ONE UBLKCP for the 32 KB W
    // tile + 32 x-row bulks, mbarrier expect_tx completion. This removes the
    // ~2176 LDGSTS instrs/i (rt=8 cyc/SMSP each) that bound R5-R9.
    // Double-buffered on two mbarriers; wait parity = (it>>1)&1.
    {
        float4* swbuf = (float4*)smem;                     // [2][2048] float4
        float*  sxbuf = (float*)(smem + XBUF_OFF);         // [2][512] float

        const int t    = threadIdx.x;
        const int lane = t & 31;
        const int wid  = t >> 5;
        const int oq   = wid >> 3;       // o-quarter (0..3)
        const int bg   = wid & 7;        // b-group (4 b each)
        const int bx   = blockIdx.x;
        const int n    = (II - bx + nb - 1) / nb;
        const int qidx = oq * 32 + lane;            // float4 index within a c-row
        const int obase = oq * 128 + lane * 4;

        const unsigned sb  = (unsigned)__cvta_generic_to_shared(smem);
        const unsigned mb0 = sb + MBAR_OFF;
        const unsigned mb1 = sb + MBAR_OFF + 8;

        ull sacc[4][2];
#pragma unroll
        for (int j = 0; j < 4; j++) { sacc[j][0] = 0ull; sacc[j][1] = 0ull; }

        if (t == 0) { MBAR_INIT(mb0, 1); MBAR_INIT(mb1, 1); }
        __syncthreads();

        // prologue: issue bulk loads for it=0 into buffer 0 / mb0
        if (t == 0) {
            MBAR_EXPECT(mb0, TX_BYTES);
            bulk_g2s(sb, w + (size_t)bx * CC * OO, 32768, mb0);
#pragma unroll 4
            for (int b2 = 0; b2 < BB; b2++)
                bulk_g2s(sb + XBUF_OFF + b2 * 64,
                         x + ((size_t)b2 * II + bx) * CC, 64, mb0);
        }

        for (int it = 0; it < n; it++) {
            const int i = bx + it * nb;
            const bool hn = (it + 1) < n;
            const int buf = it & 1;

            // issue bulk loads for it+1 into the other buffer/mbar
            if (hn && t == 0) {
                const int i2 = i + nb;
                const unsigned mbn = buf ? mb0 : mb1;
                const unsigned so  = (1 - buf);
                MBAR_EXPECT(mbn, TX_BYTES);
                bulk_g2s(sb + so * 32768, w + (size_t)i2 * CC * OO, 32768, mbn);
#pragma unroll 4
                for (int b2 = 0; b2 < BB; b2++)
                    bulk_g2s(sb + XBUF_OFF + so * 2048 + b2 * 64,
                             x + ((size_t)b2 * II + i2) * CC, 64, mbn);
            }

            // wait for this iteration's data
            mbar_wait(buf ? mb1 : mb0, (unsigned)((it >> 1) & 1));
            __syncthreads();

            const float4* sw4 = swbuf + buf * WBUF_F4;
            const float*  sxp = sxbuf + buf * 512;

            ull acc[4][2];
#pragma unroll
            for (int j = 0; j < 4; j++) { acc[j][0] = 0ull; acc[j][1] = 0ull; }

#pragma unroll
            for (int c = 0; c < CC; c++) {
                const float4 wa = sw4[c * 128 + qidx];
                const ull wv0 = pack2(wa.x, wa.y);
                const ull wv1 = pack2(wa.z, wa.w);
#pragma unroll
                for (int bb = 0; bb < 4; bb++) {
                    const float xs = sxp[(bg * 4 + bb) * CC + c];   // warp-uniform broadcast
                    const ull xx = pack2(xs, xs);
                    fma2(acc[bb][0], xx, wv0);
                    fma2(acc[bb][1], xx, wv1);
                }
            }

            // store fp16 votes (256 B coalesced per warp per bb) + iter0 partials
#pragma unroll
            for (int bb = 0; bb < 4; bb++) {
                const int b = bg * 4 + bb;
                float l0, h0, l1, h1;
                unpack2(acc[bb][0], l0, h0);
                unpack2(acc[bb][1], l1, h1);
                __half2 hh[2] = { __floats2half2_rn(l0, h0), __floats2half2_rn(l1, h1) };
                *(uint2*)(g_votes + ((size_t)i * BB + b) * OO + obase) = *(uint2*)hh;
                add2(sacc[bb][0], acc[bb][0]);
                add2(sacc[bb][1], acc[bb][1]);
            }
            __syncthreads();   // all reads of this buffer done before TMA refill
        }

        // deterministic per-block partial write (row = blockIdx.x)
#pragma unroll
        for (int bb = 0; bb < 4; bb++) {
            const int b = bg * 4 + bb;
            float l0, h0, l1, h1;
            unpack2(sacc[bb][0], l0, h0);
            unpack2(sacc[bb][1], l1, h1);
            *(float4*)(g_part + (size_t)bx * BO + b * OO + obase) = make_float4(l0, h0, l1, h1);
        }
    }

    grid_sync(nb);
    squash_phase(smem, nb, 1.0f / 32.0f, bias, g_actS, 0);  // actS = act0
    grid_sync(nb);
    route_phase<0>(nb);                                     // softmax(u(act0)); keep votes in L2
    grid_sync(nb);
    squash_phase(smem, nb, 1.0f, bias, g_actS, 1);          // actS = act0 + act1
    grid_sync(nb);
    route_phase<1>(nb);                                     // softmax(u(act0+act1)); streaming reads
    grid_sync(nb);
    squash_phase(smem, nb, 1.0f, bias, out, 0);             // final activation
}

// ---------------------------------------------------------------------------
extern "C" void kernel_launch(void* const* d_in, const int* in_sizes, int n_in,
                              void* d_out, int out_size) {
    const float* x    = (const float*)d_in[0];
    const float* w    = (const float*)d_in[1];
    const float* bias = (const float*)d_in[2];
    float* out = (float*)d_out;

    int dev = 0, sm = 148;
    cudaGetDevice(&dev);
    cudaDeviceGetAttribute(&sm, cudaDevAttrMultiProcessorCount, dev);
    int nb = sm < NBMAX ? sm : NBMAX;
    if (nb < 128) nb = 128;  // squash uses 128 blocks; all real targets have >=128 SMs

    cudaFuncSetAttribute(caps_kernel, cudaFuncAttributeMaxDynamicSharedMemorySize, SMEM_TOTAL);
    caps_kernel<<<nb, NT, SMEM_TOTAL>>>(x, w, bias, out, nb);
}

// round 11
// speedup vs baseline: 1.2002x; 1.2002x over previous
#include <cuda_runtime.h>
#include <cuda_fp16.h>
#include <cstdint>

// Problem constants (fixed by the dataset)
#define BB 32      // batch
#define II 2048    // input capsules
#define CC 16      // input atoms (contraction dim)
#define DD 32      // output capsules
#define AA 16      // output atoms
#define OO 512     // DD*AA
#define BO (BB*OO) // 16384
#define NBMAX 160
#define NT 1024

typedef unsigned long long ull;

// Scratch (static __device__ arrays: no dynamic allocation)
__device__ __half g_votes[(size_t)II * BB * OO];     // [i][b][o] fp16, 67 MB
__device__ float  g_part[(size_t)NBMAX * BO];        // per-block partials, 10.5 MB
__device__ float  g_actS[BO];                        // act0, then act0+act1
__device__ unsigned g_count;                          // barrier arrive counter (self-resetting)
__device__ volatile unsigned g_sense;                 // barrier generation (monotonic)

// ---------------- packed f32x2 helpers (route phase) ----------------
__device__ __forceinline__ ull pack2(float lo, float hi) {
    ull r; asm("mov.b64 %0, {%1,%2};" : "=l"(r) : "f"(lo), "f"(hi)); return r;
}
__device__ __forceinline__ void unpack2(ull v, float& lo, float& hi) {
    asm("mov.b64 {%0,%1}, %2;" : "=f"(lo), "=f"(hi) : "l"(v));
}
__device__ __forceinline__ void fma2(ull& d, ull a, ull b) {
    asm("fma.rn.f32x2 %0, %1, %2, %0;" : "+l"(d) : "l"(a), "l"(b));
}

// ---------------- mma helpers ----------------
__device__ __forceinline__ void ldsm_x4(unsigned& r0, unsigned& r1, unsigned& r2, unsigned& r3,
                                        unsigned addr) {
    asm volatile("ldmatrix.sync.aligned.m8n8.x4.shared.b16 {%0,%1,%2,%3}, [%4];"
                 : "=r"(r0), "=r"(r1), "=r"(r2), "=r"(r3) : "r"(addr));
}
__device__ __forceinline__ void ldsm_x4_trans(unsigned& r0, unsigned& r1, unsigned& r2, unsigned& r3,
                                              unsigned addr) {
    asm volatile("ldmatrix.sync.aligned.m8n8.x4.trans.shared.b16 {%0,%1,%2,%3}, [%4];"
                 : "=r"(r0), "=r"(r1), "=r"(r2), "=r"(r3) : "r"(addr));
}
__device__ __forceinline__ void mma16816(float& d0, float& d1, float& d2, float& d3,
                                         unsigned a0, unsigned a1, unsigned a2, unsigned a3,
                                         unsigned b0, unsigned b1) {
    asm volatile(
        "mma.sync.aligned.m16n8k16.row.col.f32.f16.f16.f32 "
        "{%0,%1,%2,%3}, {%4,%5,%6,%7}, {%8,%9}, {%10,%11,%12,%13};"
        : "=f"(d0), "=f"(d1), "=f"(d2), "=f"(d3)
        : "r"(a0), "r"(a1), "r"(a2), "r"(a3), "r"(b0), "r"(b1),
          "f"(0.f), "f"(0.f), "f"(0.f), "f"(0.f));
}
__device__ __forceinline__ unsigned cvt_h2(float hi, float lo) {
    unsigned v; asm("cvt.rn.f16x2.f32 %0, %1, %2;" : "=r"(v) : "f"(hi), "f"(lo)); return v;
}

// smem layout: W fp16 buffers [2][16384 B] @0; x fp16 buffers [2][1536 B] @32768
#define WBUF_BYTES 16384
#define XBUF_OFF   32768
#define XBUF_BYTES 1536              // 32 rows x 48 B (16 fp16 data + 16 B pad)
#define SMEM_TOTAL (32768 + 2*XBUF_BYTES + 128)   // 35968; squash needs 17 KB (fits)

// ---------------------------------------------------------------------------
// Software grid barrier (sense-reversing). nb blocks co-resident (1/SM).
// ---------------------------------------------------------------------------
__device__ __forceinline__ void grid_sync(int nb) {
    __syncthreads();
    if (threadIdx.x == 0) {
        unsigned gen = g_sense;
        __threadfence();
        if (atomicAdd(&g_count, 1u) == (unsigned)(nb - 1)) {
            g_count = 0;
            __threadfence();
            g_sense = gen + 1;
        } else {
            while (g_sense == gen) __nanosleep(32);
        }
        __threadfence();
    }
    __syncthreads();
}

// ---------------------------------------------------------------------------
// Squash phase: blocks 0..127 active; block -> (b = bx>>2, oq4 = bx&3).
// 1024 threads = 32 float4-cols x 32 k-slices; smem tree; lane groups of 4
// = one 16-atom capsule. Fixed order -> deterministic.
// ---------------------------------------------------------------------------
__device__ __forceinline__ void squash_phase(char* smem, int nb, float scale,
                                             const float* __restrict__ bias,
                                             float* __restrict__ dst, int accumulate) {
    if (blockIdx.x < 128) {
        float4* red = (float4*)smem;                 // [32][33] float4 (17 KB)
        const int b    = blockIdx.x >> 2;
        const int oq4  = blockIdx.x & 3;
        const int col  = threadIdx.x & 31;
        const int ks   = threadIdx.x >> 5;
        const int gcol = b * 128 + oq4 * 32 + col;   // global float4 column
        const float4* gp = (const float4*)g_part;

        float4 s = make_float4(0.f, 0.f, 0.f, 0.f);
        for (int k = ks; k < nb; k += 32) {
            float4 v = gp[(size_t)k * (BO / 4) + gcol];
            s.x += v.x; s.y += v.y; s.z += v.z; s.w += v.w;
        }
        red[ks * 33 + col] = s;
        __syncthreads();

        if (threadIdx.x < 32) {
            float4 sum = red[col];
#pragma unroll
            for (int j = 1; j < 32; j++) {
                float4 v = red[j * 33 + col];
                sum.x += v.x; sum.y += v.y; sum.z += v.z; sum.w += v.w;
            }
            const float4 bi = ((const float4*)bias)[oq4 * 32 + col];
            float4 val;
            val.x = fmaf(sum.x, scale, bi.x);
            val.y = fmaf(sum.y, scale, bi.y);
            val.z = fmaf(sum.z, scale, bi.z);
            val.w = fmaf(sum.w, scale, bi.w);

            float n2 = (val.x * val.x + val.y * val.y) + (val.z * val.z + val.w * val.w);
            n2 += __shfl_xor_sync(0xffffffffu, n2, 1);
            n2 += __shfl_xor_sync(0xffffffffu, n2, 2);
            const float f = sqrtf(n2) / (1.f + n2);

            float4* dp = (float4*)dst + gcol;
            if (accumulate) {
                float4 cur = *dp;
                cur.x = fmaf(val.x, f, cur.x); cur.y = fmaf(val.y, f, cur.y);
                cur.z = fmaf(val.z, f, cur.z); cur.w = fmaf(val.w, f, cur.w);
                *dp = cur;
            } else {
                *dp = make_float4(val.x * f, val.y * f, val.z * f, val.w * f);
            }
        }
    }
    __syncthreads();
}

// ---------------------------------------------------------------------------
// Route phase: block bx owns i in [ilo, ihi); warp = one b; lane = one d.
// STREAM=1 (pass 2): __ldcs streaming (votes dead after; keeps DRAM quiet).
// Prefetch next i before the softmax chain; dot and accumulate in f32x2.
// ---------------------------------------------------------------------------
template <int STREAM>
__device__ __forceinline__ void route_phase(int nb) {
    const int b    = threadIdx.x >> 5;
    const int lane = threadIdx.x & 31;
    const int bx   = blockIdx.x;
    const int ilo  = (bx * II) / nb;
    const int ihi  = ((bx + 1) * II) / nb;
    const int d    = lane;

    ull arp[8];
    {
        const float4* ap = (const float4*)(g_actS + (b * DD + d) * AA);
        float4 a0 = ap[0], a1 = ap[1], a2 = ap[2], a3 = ap[3];
        arp[0] = pack2(a0.x, a0.y); arp[1] = pack2(a0.z, a0.w);
        arp[2] = pack2(a1.x, a1.y); arp[3] = pack2(a1.z, a1.w);
        arp[4] = pack2(a2.x, a2.y); arp[5] = pack2(a2.z, a2.w);
        arp[6] = pack2(a3.x, a3.y); arp[7] = pack2(a3.z, a3.w);
    }

    ull acc[8];
#pragma unroll
    for (int k = 0; k < 8; k++) acc[k] = 0ull;

    const uint4* vbase = (const uint4*)(g_votes + (size_t)b * OO + d * 16);
    const int stride = (BB * OO) / 8;                 // uint4 stride per i
    uint4 p0 = STREAM ? __ldcs(vbase + (size_t)ilo * stride)
                      : __ldg(vbase + (size_t)ilo * stride);
    uint4 p1 = STREAM ? __ldcs(vbase + (size_t)ilo * stride + 1)
                      : __ldg(vbase + (size_t)ilo * stride + 1);

    for (int i = ilo; i < ihi; i++) {
        uint4 c0 = p0, c1 = p1;
        if (i + 1 < ihi) {                    // prefetch next i before the chain
            const uint4* np = vbase + (size_t)(i + 1) * stride;
            p0 = STREAM ? __ldcs(np)     : __ldg(np);
            p1 = STREAM ? __ldcs(np + 1) : __ldg(np + 1);
        }

        ull vpk[8];
        {
            const __half2* h0 = (const __half2*)&c0;
            const __half2* h1 = (const __half2*)&c1;
#pragma unroll
            for (int j = 0; j < 4; j++) {
                float2 f = __half22float2(h0[j]); vpk[j]     = pack2(f.x, f.y);
                float2 g = __half22float2(h1[j]); vpk[4 + j] = pack2(g.x, g.y);
            }
        }

        ull u2 = 0ull;
#pragma unroll
        for (int k = 0; k < 8; k++) fma2(u2, vpk[k], arp[k]);
        float ulo, uhi; unpack2(u2, ulo, uhi);
        const float u = ulo + uhi;

        // softmax over d (32 lanes); |u| small enough to skip max-subtract
        float e = __expf(u);
        float s = e;
#pragma unroll
        for (int o = 16; o >= 1; o >>= 1) s += __shfl_xor_sync(0xffffffffu, s, o);
        const float r = __fdividef(e, s);
        const ull rr = pack2(r, r);
#pragma unroll
        for (int k = 0; k < 8; k++) fma2(acc[k], rr, vpk[k]);
    }

    float* dst = g_part + (size_t)bx * BO + (b * DD + d) * AA;
#pragma unroll
    for (int k = 0; k < 4; k++) {
        float l0, h0, l1, h1;
        unpack2(acc[2 * k], l0, h0);
        unpack2(acc[2 * k + 1], l1, h1);
        ((float4*)dst)[k] = make_float4(l0, h0, l1, h1);
    }
}

// ---------------------------------------------------------------------------
// Fused persistent kernel.
// ---------------------------------------------------------------------------
__global__ __launch_bounds__(NT, 1) void caps_kernel(const float* __restrict__ x,
                                                     const float* __restrict__ w,
                                                     const float* __restrict__ bias,
                                                     float* __restrict__ out,
                                                     int nb) {
    extern __shared__ __align__(16) char smem[];

    // ================= Phase 1: votes (HMMA) =================
    // Per i: D[32b,512o] = A[32b,16c] x B[16c,512o], fp16 in / fp32 acc via
    // mma.sync.m16n8k16. W/x converted fp32->fp16 during double-buffered
    // staging (LDG.128 -> CVT -> STS.128, one __syncthreads per i).
    // W smem: 16 rows x 64 chunks(16 B), chunk swizzle j^(k&7) -> conflict-free
    // ldmatrix. x smem: 32 rows x 48 B (32 B data + pad) -> conflict-free A.
    // Warp w: mh=w&1 (16-row b half), ng=w>>1 (32-col o group, 4 n-tiles).
    {
        const int t    = threadIdx.x;
        const int lane = t & 31;
        const int wid  = t >> 5;
        const int mh   = wid & 1;
        const int ng   = wid >> 1;          // 0..15
        const int bx   = blockIdx.x;
        const int n    = (II - bx + nb - 1) / nb;

        const unsigned sb = (unsigned)__cvta_generic_to_shared(smem);

        // staging roles
        const int wk = t >> 6;              // W row (c) 0..15
        const int wj = t & 63;              // W chunk 0..63
        const unsigned wst = sb + wk * 1024 + ((wj ^ (wk & 7)) << 4);
        const int xb = t >> 2, xq = t & 3;  // x role (t < 128)
        const unsigned xst = sb + XBUF_OFF + xb * 48 + xq * 8;

        // ldmatrix source addresses (within buffer 0; add buf offsets later)
        const int al = lane & 15, ak = lane >> 4;
        const unsigned aaddr = sb + XBUF_OFF + (mh * 16 + al) * 48 + ak * 16;
        const int bk = lane & 15, bjo = lane >> 4;
        // B group g2 covers n-chunks j0 = ng*4 + g2*2 + bjo
        unsigned baddr[2];
#pragma unroll
        for (int g2 = 0; g2 < 2; g2++) {
            int j = ng * 4 + g2 * 2 + bjo;
            baddr[g2] = sb + bk * 1024 + ((j ^ (bk & 7)) << 4);
        }

        const int g  = lane >> 2;           // fragment row group
        const int tq = lane & 3;            // fragment col quad
        const int brow0 = mh * 16 + g;

        float sacc[16];
#pragma unroll
        for (int k = 0; k < 16; k++) sacc[k] = 0.f;

        // prologue: load W(bx), x(bx) fp32 into registers
        float4 wr0, wr1, xr;
        {
            const float4* ws = (const float4*)(w + (size_t)bx * CC * OO + wk * OO + wj * 8);
            wr0 = __ldcs(ws); wr1 = __ldcs(ws + 1);
            if (t < 128)
                xr = __ldcs((const float4*)(x + ((size_t)xb * II + bx) * CC) + xq);
        }

        for (int it = 0; it < n; it++) {
            const int i = bx + it * nb;
            const bool hn = (it + 1) < n;
            const int buf = it & 1;
            const unsigned wb = buf * WBUF_BYTES;
            const unsigned xbo = buf * XBUF_BYTES;

            // stage fp16 tiles (cvt in regs, one STS.128 / STS.64)
            {
                unsigned h[4];
                h[0] = cvt_h2(wr0.y, wr0.x); h[1] = cvt_h2(wr0.w, wr0.z);
                h[2] = cvt_h2(wr1.y, wr1.x); h[3] = cvt_h2(wr1.w, wr1.z);
                asm volatile("st.shared.v4.b32 [%0], {%1,%2,%3,%4};"
                             :: "r"(wst + wb), "r"(h[0]), "r"(h[1]), "r"(h[2]), "r"(h[3]));
                if (t < 128) {
                    unsigned x0 = cvt_h2(xr.y, xr.x), x1 = cvt_h2(xr.w, xr.z);
                    asm volatile("st.shared.v2.b32 [%0], {%1,%2};"
                                 :: "r"(xst + xbo), "r"(x0), "r"(x1));
                }
            }
            __syncthreads();

            // issue fp32 loads for it+1 (latency hidden behind compute)
            if (hn) {
                const int i2 = i + nb;
                const float4* ws = (const float4*)(w + (size_t)i2 * CC * OO + wk * OO + wj * 8);
                wr0 = __ldcs(ws); wr1 = __ldcs(ws + 1);
                if (t < 128)
                    xr = __ldcs((const float4*)(x + ((size_t)xb * II + i2) * CC) + xq);
            }

            // A fragment (x): one ldmatrix.x4
            unsigned a0, a1, a2, a3;
            ldsm_x4(a0, a1, a2, a3, aaddr + xbo);

            __half* vrow = g_votes + ((size_t)i * BB + brow0) * OO;
#pragma unroll
            for (int g2 = 0; g2 < 2; g2++) {
                unsigned b0, b1, b2, b3;
                ldsm_x4_trans(b0, b1, b2, b3, baddr[g2] + wb);
#pragma unroll
                for (int nt = 0; nt < 2; nt++) {
                    float d0, d1, d2, d3;
                    mma16816(d0, d1, d2, d3, a0, a1, a2, a3,
                             nt ? b2 : b0, nt ? b3 : b1);
                    const int ntile = g2 * 2 + nt;
                    const int o = (ng * 4 + ntile) * 8 + tq * 2;
                    *(unsigned*)((__half*)vrow + o)            = cvt_h2(d1, d0);
                    *(unsigned*)((__half*)vrow + 8 * OO + o)   = cvt_h2(d3, d2);
                    const int s = ntile * 4;
                    sacc[s] += d0; sacc[s + 1] += d1; sacc[s + 2] += d2; sacc[s + 3] += d3;
                }
            }
            // no trailing sync: next iteration stages the other buffer; its
            // __syncthreads orders all reads of this buffer before refill.
        }

        // deterministic per-block partial write (row = blockIdx.x)
        float* pr = g_part + (size_t)bx * BO;
#pragma unroll
        for (int ntile = 0; ntile < 4; ntile++) {
            const int o = (ng * 4 + ntile) * 8 + tq * 2;
            const int s = ntile * 4;
            *(float2*)(pr + brow0 * OO + o)       = make_float2(sacc[s],     sacc[s + 1]);
            *(float2*)(pr + (brow0 + 8) * OO + o) = make_float2(sacc[s + 2], sacc[s + 3]);
        }
    }

    grid_sync(nb);
    squash_phase(smem, nb, 1.0f / 32.0f, bias, g_actS, 0);  // actS = act0
    grid_sync(nb);
    route_phase<0>(nb);                                     // softmax(u(act0)); keep votes in L2
    grid_sync(nb);
    squash_phase(smem, nb, 1.0f, bias, g_actS, 1);          // actS = act0 + act1
    grid_sync(nb);
    route_phase<1>(nb);                                     // softmax(u(act0+act1)); streaming reads
    grid_sync(nb);
    squash_phase(smem, nb, 1.0f, bias, out, 0);             // final activation
}

// ---------------------------------------------------------------------------
extern "C" void kernel_launch(void* const* d_in, const int* in_sizes, int n_in,
                              void* d_out, int out_size) {
    const float* x    = (const float*)d_in[0];
    const float* w    = (const float*)d_in[1];
    const float* bias = (const float*)d_in[2];
    float* out = (float*)d_out;

    int dev = 0, sm = 148;
    cudaGetDevice(&dev);
    cudaDeviceGetAttribute(&sm, cudaDevAttrMultiProcessorCount, dev);
    int nb = sm < NBMAX ? sm : NBMAX;
    if (nb < 128) nb = 128;  // squash uses 128 blocks; all real targets have >=128 SMs

    cudaFuncSetAttribute(caps_kernel, cudaFuncAttributeMaxDynamicSharedMemorySize, SMEM_TOTAL);
    caps_kernel<<<nb, NT, SMEM_TOTAL>>>(x, w, bias, out, nb);
}

// round 12
// speedup vs baseline: 1.2472x; 1.0392x over previous
#include <cuda_runtime.h>
#include <cuda_fp16.h>
#include <cstdint>

// Problem constants (fixed by the dataset)
#define BB 32      // batch
#define II 2048    // input capsules
#define CC 16      // input atoms (contraction dim)
#define DD 32      // output capsules
#define AA 16      // output atoms
#define OO 512     // DD*AA
#define BO (BB*OO) // 16384
#define NBMAX 160
#define NT 1024

typedef unsigned long long ull;

// Scratch (static __device__ arrays: no dynamic allocation)
__device__ __half g_votes[(size_t)II * BB * OO];     // [i][b][o] fp16, 67 MB
__device__ float  g_part[(size_t)NBMAX * BO];        // per-block partials, 10.5 MB
__device__ float  g_actS[BO];                        // act0, then act0+act1
__device__ unsigned g_count;                          // barrier arrive counter (self-resetting)
__device__ volatile unsigned g_sense;                 // barrier generation (monotonic)

// ---------------- packed f32x2 helpers (route phase) ----------------
__device__ __forceinline__ ull pack2(float lo, float hi) {
    ull r; asm("mov.b64 %0, {%1,%2};" : "=l"(r) : "f"(lo), "f"(hi)); return r;
}
__device__ __forceinline__ void unpack2(ull v, float& lo, float& hi) {
    asm("mov.b64 {%0,%1}, %2;" : "=f"(lo), "=f"(hi) : "l"(v));
}
__device__ __forceinline__ void fma2(ull& d, ull a, ull b) {
    asm("fma.rn.f32x2 %0, %1, %2, %0;" : "+l"(d) : "l"(a), "l"(b));
}

// ---------------- mma helpers ----------------
__device__ __forceinline__ void ldsm_x4(unsigned& r0, unsigned& r1, unsigned& r2, unsigned& r3,
                                        unsigned addr) {
    asm volatile("ldmatrix.sync.aligned.m8n8.x4.shared.b16 {%0,%1,%2,%3}, [%4];"
                 : "=r"(r0), "=r"(r1), "=r"(r2), "=r"(r3) : "r"(addr));
}
__device__ __forceinline__ void ldsm_x4_trans(unsigned& r0, unsigned& r1, unsigned& r2, unsigned& r3,
                                              unsigned addr) {
    asm volatile("ldmatrix.sync.aligned.m8n8.x4.trans.shared.b16 {%0,%1,%2,%3}, [%4];"
                 : "=r"(r0), "=r"(r1), "=r"(r2), "=r"(r3) : "r"(addr));
}
__device__ __forceinline__ void mma16816(float& d0, float& d1, float& d2, float& d3,
                                         unsigned a0, unsigned a1, unsigned a2, unsigned a3,
                                         unsigned b0, unsigned b1) {
    asm volatile(
        "mma.sync.aligned.m16n8k16.row.col.f32.f16.f16.f32 "
        "{%0,%1,%2,%3}, {%4,%5,%6,%7}, {%8,%9}, {%10,%11,%12,%13};"
        : "=f"(d0), "=f"(d1), "=f"(d2), "=f"(d3)
        : "r"(a0), "r"(a1), "r"(a2), "r"(a3), "r"(b0), "r"(b1),
          "f"(0.f), "f"(0.f), "f"(0.f), "f"(0.f));
}
__device__ __forceinline__ unsigned cvt_h2(float hi, float lo) {
    unsigned v; asm("cvt.rn.f16x2.f32 %0, %1, %2;" : "=r"(v) : "f"(hi), "f"(lo)); return v;
}

// smem layout: W fp16 [2][16384] @0; x fp16 [2][1536] @32768; vote stage @35840
#define WBUF_BYTES 16384
#define XBUF_OFF   32768
#define XBUF_BYTES 1536              // 32 rows x 48 B (32 B data + 16 B pad)
#define VSTAGE_OFF 35840
#define VROW_B     1040              // 1024 B data + 16 B pad (bank shift of 4)
#define SMEM_TOTAL (VSTAGE_OFF + BB * VROW_B + 64)   // ~69184; squash's 17 KB fits

// ---------------------------------------------------------------------------
// Software grid barrier (sense-reversing). nb blocks co-resident (1/SM).
// ---------------------------------------------------------------------------
__device__ __forceinline__ void grid_sync(int nb) {
    __syncthreads();
    if (threadIdx.x == 0) {
        unsigned gen = g_sense;
        __threadfence();
        if (atomicAdd(&g_count, 1u) == (unsigned)(nb - 1)) {
            g_count = 0;
            __threadfence();
            g_sense = gen + 1;
        } else {
            while (g_sense == gen) __nanosleep(32);
        }
        __threadfence();
    }
    __syncthreads();
}

// ---------------------------------------------------------------------------
// Squash phase: blocks 0..127 active; block -> (b = bx>>2, oq4 = bx&3).
// 1024 threads = 32 float4-cols x 32 k-slices; smem tree; lane groups of 4
// = one 16-atom capsule. Fixed order -> deterministic.
// ---------------------------------------------------------------------------
__device__ __forceinline__ void squash_phase(char* smem, int nb, float scale,
                                             const float* __restrict__ bias,
                                             float* __restrict__ dst, int accumulate) {
    if (blockIdx.x < 128) {
        float4* red = (float4*)smem;                 // [32][33] float4 (17 KB)
        const int b    = blockIdx.x >> 2;
        const int oq4  = blockIdx.x & 3;
        const int col  = threadIdx.x & 31;
        const int ks   = threadIdx.x >> 5;
        const int gcol = b * 128 + oq4 * 32 + col;   // global float4 column
        const float4* gp = (const float4*)g_part;

        float4 s = make_float4(0.f, 0.f, 0.f, 0.f);
        for (int k = ks; k < nb; k += 32) {
            float4 v = gp[(size_t)k * (BO / 4) + gcol];
            s.x += v.x; s.y += v.y; s.z += v.z; s.w += v.w;
        }
        red[ks * 33 + col] = s;
        __syncthreads();

        if (threadIdx.x < 32) {
            float4 sum = red[col];
#pragma unroll
            for (int j = 1; j < 32; j++) {
                float4 v = red[j * 33 + col];
                sum.x += v.x; sum.y += v.y; sum.z += v.z; sum.w += v.w;
            }
            const float4 bi = ((const float4*)bias)[oq4 * 32 + col];
            float4 val;
            val.x = fmaf(sum.x, scale, bi.x);
            val.y = fmaf(sum.y, scale, bi.y);
            val.z = fmaf(sum.z, scale, bi.z);
            val.w = fmaf(sum.w, scale, bi.w);

            float n2 = (val.x * val.x + val.y * val.y) + (val.z * val.z + val.w * val.w);
            n2 += __shfl_xor_sync(0xffffffffu, n2, 1);
            n2 += __shfl_xor_sync(0xffffffffu, n2, 2);
            const float f = sqrtf(n2) / (1.f + n2);

            float4* dp = (float4*)dst + gcol;
            if (accumulate) {
                float4 cur = *dp;
                cur.x = fmaf(val.x, f, cur.x); cur.y = fmaf(val.y, f, cur.y);
                cur.z = fmaf(val.z, f, cur.z); cur.w = fmaf(val.w, f, cur.w);
                *dp = cur;
            } else {
                *dp = make_float4(val.x * f, val.y * f, val.z * f, val.w * f);
            }
        }
    }
    __syncthreads();
}

// ---------------------------------------------------------------------------
// Route phase: block bx owns i in [ilo, ihi); warp = one b; lane = one d.
// STREAM=1 (pass 2): __ldcs streaming (votes dead after; keeps DRAM quiet).
// Prefetch next i before the softmax chain; dot and accumulate in f32x2.
// ---------------------------------------------------------------------------
template <int STREAM>
__device__ __forceinline__ void route_phase(int nb) {
    const int b    = threadIdx.x >> 5;
    const int lane = threadIdx.x & 31;
    const int bx   = blockIdx.x;
    const int ilo  = (bx * II) / nb;
    const int ihi  = ((bx + 1) * II) / nb;
    const int d    = lane;

    ull arp[8];
    {
        const float4* ap = (const float4*)(g_actS + (b * DD + d) * AA);
        float4 a0 = ap[0], a1 = ap[1], a2 = ap[2], a3 = ap[3];
        arp[0] = pack2(a0.x, a0.y); arp[1] = pack2(a0.z, a0.w);
        arp[2] = pack2(a1.x, a1.y); arp[3] = pack2(a1.z, a1.w);
        arp[4] = pack2(a2.x, a2.y); arp[5] = pack2(a2.z, a2.w);
        arp[6] = pack2(a3.x, a3.y); arp[7] = pack2(a3.z, a3.w);
    }

    ull acc[8];
#pragma unroll
    for (int k = 0; k < 8; k++) acc[k] = 0ull;

    const uint4* vbase = (const uint4*)(g_votes + (size_t)b * OO + d * 16);
    const int stride = (BB * OO) / 8;                 // uint4 stride per i
    uint4 p0 = STREAM ? __ldcs(vbase + (size_t)ilo * stride)
                      : __ldg(vbase + (size_t)ilo * stride);
    uint4 p1 = STREAM ? __ldcs(vbase + (size_t)ilo * stride + 1)
                      : __ldg(vbase + (size_t)ilo * stride + 1);

    for (int i = ilo; i < ihi; i++) {
        uint4 c0 = p0, c1 = p1;
        if (i + 1 < ihi) {                    // prefetch next i before the chain
            const uint4* np = vbase + (size_t)(i + 1) * stride;
            p0 = STREAM ? __ldcs(np)     : __ldg(np);
            p1 = STREAM ? __ldcs(np + 1) : __ldg(np + 1);
        }

        ull vpk[8];
        {
            const __half2* h0 = (const __half2*)&c0;
            const __half2* h1 = (const __half2*)&c1;
#pragma unroll
            for (int j = 0; j < 4; j++) {
                float2 f = __half22float2(h0[j]); vpk[j]     = pack2(f.x, f.y);
                float2 g = __half22float2(h1[j]); vpk[4 + j] = pack2(g.x, g.y);
            }
        }

        ull u2 = 0ull;
#pragma unroll
        for (int k = 0; k < 8; k++) fma2(u2, vpk[k], arp[k]);
        float ulo, uhi; unpack2(u2, ulo, uhi);
        const float u = ulo + uhi;

        // softmax over d (32 lanes); |u| small enough to skip max-subtract
        float e = __expf(u);
        float s = e;
#pragma unroll
        for (int o = 16; o >= 1; o >>= 1) s += __shfl_xor_sync(0xffffffffu, s, o);
        const float r = __fdividef(e, s);
        const ull rr = pack2(r, r);
#pragma unroll
        for (int k = 0; k < 8; k++) fma2(acc[k], rr, vpk[k]);
    }

    float* dst = g_part + (size_t)bx * BO + (b * DD + d) * AA;
#pragma unroll
    for (int k = 0; k < 4; k++) {
        float l0, h0, l1, h1;
        unpack2(acc[2 * k], l0, h0);
        unpack2(acc[2 * k + 1], l1, h1);
        ((float4*)dst)[k] = make_float4(l0, h0, l1, h1);
    }
}

// ---------------------------------------------------------------------------
// Fused persistent kernel.
// ---------------------------------------------------------------------------
__global__ __launch_bounds__(NT, 1) void caps_kernel(const float* __restrict__ x,
                                                     const float* __restrict__ w,
                                                     const float* __restrict__ bias,
                                                     float* __restrict__ out,
                                                     int nb) {
    extern __shared__ __align__(16) char smem[];

    // ================= Phase 1: votes (HMMA + smem-staged stores) ==========
    // Per i: D[32b,512o] = A[32b,16c] x B[16c,512o] via mma.sync.m16n8k16.
    // Fragments are staged in padded smem ([b][1040 B] rows, conflict-free
    // STS.32), then written out as contiguous STG.128 (32 KB per (block,i)).
    // This replaces the 8-sector scattered STG.32s that bound R11 in L1.
    {
        const int t    = threadIdx.x;
        const int lane = t & 31;
        const int wid  = t >> 5;
        const int mh   = wid & 1;
        const int ng   = wid >> 1;          // 0..15
        const int bx   = blockIdx.x;
        const int n    = (II - bx + nb - 1) / nb;

        const unsigned sb = (unsigned)__cvta_generic_to_shared(smem);

        // staging roles
        const int wk = t >> 6;              // W row (c) 0..15
        const int wj = t & 63;              // W chunk 0..63
        const unsigned wst = sb + wk * 1024 + ((wj ^ (wk & 7)) << 4);
        const int xb = t >> 2, xq = t & 3;  // x role (t < 128)
        const unsigned xst = sb + XBUF_OFF + xb * 48 + xq * 8;

        // ldmatrix source addresses
        const int al = lane & 15, ak = lane >> 4;
        const unsigned aaddr = sb + XBUF_OFF + (mh * 16 + al) * 48 + ak * 16;
        const int bk = lane & 15, bjo = lane >> 4;
        unsigned baddr[2];
#pragma unroll
        for (int g2 = 0; g2 < 2; g2++) {
            int j = ng * 4 + g2 * 2 + bjo;
            baddr[g2] = sb + bk * 1024 + ((j ^ (bk & 7)) << 4);
        }

        const int g  = lane >> 2;           // fragment row group
        const int tq = lane & 3;            // fragment col quad
        const int brow0 = mh * 16 + g;

        // vote staging addresses (row*1040: bank shift 4/row -> conflict-free)
        const unsigned vs0 = sb + VSTAGE_OFF + brow0 * VROW_B + ng * 64 + tq * 4;
        const unsigned vs1 = vs0 + 8 * VROW_B;
        // writeout role: thread covers chunks t and t+1024 (16 B each)
        const unsigned wo_s0 = sb + VSTAGE_OFF + (t >> 6) * VROW_B + (t & 63) * 16;
        const unsigned wo_s1 = sb + VSTAGE_OFF + ((t + 1024) >> 6) * VROW_B + (t & 63) * 16;

        float sacc[16];
#pragma unroll
        for (int k = 0; k < 16; k++) sacc[k] = 0.f;

        // prologue: load W(bx), x(bx) fp32 into registers
        float4 wr0, wr1, xr;
        {
            const float4* ws = (const float4*)(w + (size_t)bx * CC * OO + wk * OO + wj * 8);
            wr0 = __ldcs(ws); wr1 = __ldcs(ws + 1);
            if (t < 128)
                xr = __ldcs((const float4*)(x + ((size_t)xb * II + bx) * CC) + xq);
        }

        for (int it = 0; it < n; it++) {
            const int i = bx + it * nb;
            const bool hn = (it + 1) < n;
            const int buf = it & 1;
            const unsigned wb = buf * WBUF_BYTES;
            const unsigned xbo = buf * XBUF_BYTES;

            // stage fp16 W/x tiles (cvt in regs, one STS.128 / STS.64)
            {
                unsigned h[4];
                h[0] = cvt_h2(wr0.y, wr0.x); h[1] = cvt_h2(wr0.w, wr0.z);
                h[2] = cvt_h2(wr1.y, wr1.x); h[3] = cvt_h2(wr1.w, wr1.z);
                asm volatile("st.shared.v4.b32 [%0], {%1,%2,%3,%4};"
                             :: "r"(wst + wb), "r"(h[0]), "r"(h[1]), "r"(h[2]), "r"(h[3]));
                if (t < 128) {
                    unsigned x0 = cvt_h2(xr.y, xr.x), x1 = cvt_h2(xr.w, xr.z);
                    asm volatile("st.shared.v2.b32 [%0], {%1,%2};"
                                 :: "r"(xst + xbo), "r"(x0), "r"(x1));
                }
            }
            __syncthreads();   // W/x ready; also orders prev writeout before vstage reuse

            // issue fp32 loads for it+1 (latency hidden behind compute)
            if (hn) {
                const int i2 = i + nb;
                const float4* ws = (const float4*)(w + (size_t)i2 * CC * OO + wk * OO + wj * 8);
                wr0 = __ldcs(ws); wr1 = __ldcs(ws + 1);
                if (t < 128)
                    xr = __ldcs((const float4*)(x + ((size_t)xb * II + i2) * CC) + xq);
            }

            // A fragment (x): one ldmatrix.x4
            unsigned a0, a1, a2, a3;
            ldsm_x4(a0, a1, a2, a3, aaddr + xbo);

#pragma unroll
            for (int g2 = 0; g2 < 2; g2++) {
                unsigned b0, b1, b2, b3;
                ldsm_x4_trans(b0, b1, b2, b3, baddr[g2] + wb);
#pragma unroll
                for (int nt = 0; nt < 2; nt++) {
                    float d0, d1, d2, d3;
                    mma16816(d0, d1, d2, d3, a0, a1, a2, a3,
                             nt ? b2 : b0, nt ? b3 : b1);
                    const int ntile = g2 * 2 + nt;
                    const unsigned off = ntile * 16;
                    asm volatile("st.shared.b32 [%0], %1;" :: "r"(vs0 + off), "r"(cvt_h2(d1, d0)));
                    asm volatile("st.shared.b32 [%0], %1;" :: "r"(vs1 + off), "r"(cvt_h2(d3, d2)));
                    const int s = ntile * 4;
                    sacc[s] += d0; sacc[s + 1] += d1; sacc[s + 2] += d2; sacc[s + 3] += d3;
                }
            }
            __syncthreads();   // all frags staged

            // coalesced writeout: 32 KB contiguous per (block, i)
            {
                uint4 v0, v1;
                asm volatile("ld.shared.v4.b32 {%0,%1,%2,%3}, [%4];"
                             : "=r"(v0.x), "=r"(v0.y), "=r"(v0.z), "=r"(v0.w) : "r"(wo_s0));
                asm volatile("ld.shared.v4.b32 {%0,%1,%2,%3}, [%4];"
                             : "=r"(v1.x), "=r"(v1.y), "=r"(v1.z), "=r"(v1.w) : "r"(wo_s1));
                uint4* gdst = (uint4*)(g_votes + (size_t)i * BO);
                gdst[t]        = v0;
                gdst[t + 1024] = v1;
            }
        }

        // deterministic per-block partial write (row = blockIdx.x)
        float* pr = g_part + (size_t)bx * BO;
#pragma unroll
        for (int ntile = 0; ntile < 4; ntile++) {
            const int o = (ng * 4 + ntile) * 8 + tq * 2;
            const int s = ntile * 4;
            *(float2*)(pr + brow0 * OO + o)       = make_float2(sacc[s],     sacc[s + 1]);
            *(float2*)(pr + (brow0 + 8) * OO + o) = make_float2(sacc[s + 2], sacc[s + 3]);
        }
    }

    grid_sync(nb);
    squash_phase(smem, nb, 1.0f / 32.0f, bias, g_actS, 0);  // actS = act0
    grid_sync(nb);
    route_phase<0>(nb);                                     // softmax(u(act0)); keep votes in L2
    grid_sync(nb);
    squash_phase(smem, nb, 1.0f, bias, g_actS, 1);          // actS = act0 + act1
    grid_sync(nb);
    route_phase<1>(nb);                                     // softmax(u(act0+act1)); streaming reads
    grid_sync(nb);
    squash_phase(smem, nb, 1.0f, bias, out, 0);             // final activation
}

// ---------------------------------------------------------------------------
extern "C" void kernel_launch(void* const* d_in, const int* in_sizes, int n_in,
                              void* d_out, int out_size) {
    const float* x    = (const float*)d_in[0];
    const float* w    = (const float*)d_in[1];
    const float* bias = (const float*)d_in[2];
    float* out = (float*)d_out;

    int dev = 0, sm = 148;
    cudaGetDevice(&dev);
    cudaDeviceGetAttribute(&sm, cudaDevAttrMultiProcessorCount, dev);
    int nb = sm < NBMAX ? sm : NBMAX;
    if (nb < 128) nb = 128;  // squash uses 128 blocks; all real targets have >=128 SMs

    cudaFuncSetAttribute(caps_kernel, cudaFuncAttributeMaxDynamicSharedMemorySize, SMEM_TOTAL);
    caps_kernel<<<nb, NT, SMEM_TOTAL>>>(x, w, bias, out, nb);
}